// round 9
// baseline (speedup 1.0000x reference)
#include <cuda_runtime.h>
#include <cuda_fp16.h>
#include <cuda_bf16.h>
#include <cstdint>

#define MAX_NODES 100000
#define MAX_EDGES 1600000
#define D 64
#define MEGA_BLOCKS 444   // 148 SMs * 3 resident blocks (GB300 has 152 SMs; extra margin)

// ---------------- scratch (device globals) ----------------
__device__ int    g_counts[MAX_NODES + 1];   // zero on entry (BSS; re-zeroed in P3)
__device__ int    g_cursor[MAX_NODES + 1];
__device__ int    g_offsets[MAX_NODES + 1];
__device__ float  g_invdeg[MAX_NODES];
__device__ int    g_nbr[MAX_EDGES];
__device__ int    g_part[512];
__device__ __half g_xh[(size_t)MAX_NODES * D];
__device__ float  g_s1[(size_t)MAX_NODES * D];
__device__ float4 g_z[MAX_NODES];
__device__ float4 g_s[MAX_NODES];
__device__ int    g_bar_count;
__device__ int    g_bar_gen;

// ---------------- f32x2 packed helpers (sm_103a) ----------------
__device__ __forceinline__ unsigned long long pk2(float lo, float hi) {
    unsigned long long r;
    asm("mov.b64 %0, {%1, %2};" : "=l"(r) : "f"(lo), "f"(hi));
    return r;
}
__device__ __forceinline__ void fma2(unsigned long long& acc,
                                     unsigned long long a, unsigned long long b) {
    asm("fma.rn.f32x2 %0, %1, %2, %0;" : "+l"(acc) : "l"(a), "l"(b));
}
__device__ __forceinline__ float2 upk2(unsigned long long v) {
    float2 f;
    asm("mov.b64 {%0, %1}, %2;" : "=f"(f.x), "=f"(f.y) : "l"(v));
    return f;
}

// ---------------- software grid barrier (all blocks resident; single kernel) ----
__device__ __forceinline__ void grid_bar(int nb) {
    __syncthreads();
    if (threadIdx.x == 0) {
        __threadfence();
        int gen = atomicAdd(&g_bar_gen, 0);
        if (atomicAdd(&g_bar_count, 1) == nb - 1) {
            g_bar_count = 0;
            __threadfence();
            atomicExch(&g_bar_gen, gen + 1);
        } else {
            while (atomicAdd(&g_bar_gen, 0) == gen) {}
        }
        __threadfence();
    }
    __syncthreads();
}

// ---------------- the whole network in one persistent kernel ----------------
__global__ __launch_bounds__(256, 3) void mega_kernel(
    const float* __restrict__ x,
    const int*   __restrict__ esrc,
    const int*   __restrict__ edst,
    const float* __restrict__ Ws1,
    const float* __restrict__ b1,
    const float* __restrict__ Wn1,
    const float* __restrict__ Ws2,
    const float* __restrict__ b2,
    const float* __restrict__ Wn2,
    float* __restrict__ out,
    int n_nodes, int n_edges)
{
    __shared__ float Ts[64][68];    // 17408 B  (M=64 tile)
    __shared__ float Wsh[64 * 64];  // 16384 B
    __shared__ float aux[520];      // bsh | wsum | ws2+wn2+bs2 (phase-exclusive)

    const int nb  = gridDim.x;
    const int tid = threadIdx.x;
    const int gt  = blockIdx.x * 256 + tid;
    const int nthreads = nb * 256;
    const int n_tiles64 = (n_nodes + 63) >> 6;
    const int np = (n_nodes + 255) >> 8;

    const int tx = tid & 15;   // GEMM: cols tx*4..+3
    const int ty = tid >> 4;   // GEMM: rows ty*4..+3

    // ======== P0: gemm0 (g_s1 = X@Ws1 + b1, emit fp16 X) then histogram ========
    if (tid < 64) aux[tid] = b1[tid];
    #pragma unroll
    for (int r = 0; r < 4; ++r) {
        int idx = r * 256 + tid;
        *(float4*)&Wsh[idx * 4] = *(const float4*)(Ws1 + (size_t)idx * 4);
    }
    __syncthreads();

    for (int tile = blockIdx.x; tile < n_tiles64; tile += nb) {
        int m0 = tile << 6;
        // load 64x64 X tile (4 float4 per thread), fused fp16 emit
        #pragma unroll
        for (int r = 0; r < 4; ++r) {
            int m = r * 16 + (tid >> 4);
            int gm = m0 + m;
            float4 v = make_float4(0.f, 0.f, 0.f, 0.f);
            if (gm < n_nodes) {
                v = *(const float4*)(x + (size_t)gm * D + tx * 4);
                __half2 h0 = __floats2half2_rn(v.x, v.y);
                __half2 h1 = __floats2half2_rn(v.z, v.w);
                uint2 o;
                o.x = *(unsigned int*)&h0;
                o.y = *(unsigned int*)&h1;
                *(uint2*)(g_xh + (size_t)gm * D + tx * 4) = o;
            }
            *(float4*)&Ts[m][tx * 4] = v;
        }
        __syncthreads();

        unsigned long long acc2[8];
        #pragma unroll
        for (int i = 0; i < 8; ++i) acc2[i] = 0ULL;
        #pragma unroll
        for (int k0 = 0; k0 < 64; k0 += 4) {
            float4 wv[4];
            #pragma unroll
            for (int kk = 0; kk < 4; ++kk)
                wv[kk] = *(const float4*)&Wsh[(k0 + kk) * 64 + tx * 4];
            #pragma unroll
            for (int i = 0; i < 4; ++i) {
                float4 a4 = *(const float4*)&Ts[ty * 4 + i][k0];
                float av[4] = {a4.x, a4.y, a4.z, a4.w};
                #pragma unroll
                for (int kk = 0; kk < 4; ++kk) {
                    unsigned long long aa = pk2(av[kk], av[kk]);
                    fma2(acc2[i * 2],     aa, pk2(wv[kk].x, wv[kk].y));
                    fma2(acc2[i * 2 + 1], aa, pk2(wv[kk].z, wv[kk].w));
                }
            }
        }
        #pragma unroll
        for (int i = 0; i < 4; ++i) {
            int m = m0 + ty * 4 + i;
            if (m >= n_nodes) continue;
            float2 r01 = upk2(acc2[i * 2]);
            float2 r23 = upk2(acc2[i * 2 + 1]);
            float4 o;
            o.x = r01.x + aux[tx * 4 + 0];
            o.y = r01.y + aux[tx * 4 + 1];
            o.z = r23.x + aux[tx * 4 + 2];
            o.w = r23.y + aux[tx * 4 + 3];
            *(float4*)(g_s1 + (size_t)m * D + tx * 4) = o;
        }
        __syncthreads();
    }

    // histogram (counts zero on entry)
    {
        int e4n = (n_edges + 3) >> 2;
        for (int c = gt; c < e4n; c += nthreads) {
            int i4 = c * 4;
            if (i4 + 4 <= n_edges) {
                int4 d = *(const int4*)(edst + i4);
                atomicAdd(&g_counts[d.x], 1);
                atomicAdd(&g_counts[d.y], 1);
                atomicAdd(&g_counts[d.z], 1);
                atomicAdd(&g_counts[d.w], 1);
            } else {
                for (int i = i4; i < n_edges; ++i) atomicAdd(&g_counts[edst[i]], 1);
            }
        }
    }
    grid_bar(nb);

    // ======== P1: per-256-tile local exclusive scan ========
    {
        int* wsum = (int*)aux;
        for (int tile = blockIdx.x; tile < np; tile += nb) {
            int i = tile * 256 + tid;
            int c = (i < n_nodes) ? g_counts[i] : 0;
            int lane = tid & 31, wid = tid >> 5;
            int v = c;
            #pragma unroll
            for (int o = 1; o < 32; o <<= 1) {
                int u = __shfl_up_sync(0xffffffffu, v, o);
                if (lane >= o) v += u;
            }
            if (lane == 31) wsum[wid] = v;
            __syncthreads();
            if (wid == 0) {
                int w = (lane < 8) ? wsum[lane] : 0;
                #pragma unroll
                for (int o = 1; o < 8; o <<= 1) {
                    int u = __shfl_up_sync(0xffffffffu, w, o);
                    if (lane >= o) w += u;
                }
                if (lane < 8) wsum[lane] = w;
            }
            __syncthreads();
            int base = (wid > 0) ? wsum[wid - 1] : 0;
            int incl = v + base;
            if (i < n_nodes) g_offsets[i] = incl - c;
            if (tid == 255) g_part[tile] = incl;
            __syncthreads();
        }
    }
    grid_bar(nb);

    // ======== P2: per-tile base + finalize offsets/cursor/invdeg ========
    {
        int* wsum = (int*)aux;
        for (int tile = blockIdx.x; tile < np; tile += nb) {
            int s = 0;
            for (int j = tid; j < tile; j += 256) s += g_part[j];
            int lane = tid & 31, wid = tid >> 5;
            #pragma unroll
            for (int o = 16; o > 0; o >>= 1) s += __shfl_xor_sync(0xffffffffu, s, o);
            if (lane == 0) wsum[wid] = s;
            __syncthreads();
            if (tid == 0) {
                int b = 0;
                #pragma unroll
                for (int w = 0; w < 8; ++w) b += wsum[w];
                wsum[8] = b;
            }
            __syncthreads();
            int base = wsum[8];
            int i = tile * 256 + tid;
            if (i < n_nodes) {
                int off = g_offsets[i] + base;
                g_offsets[i] = off;
                g_cursor[i]  = off;
                g_invdeg[i]  = 1.0f / fmaxf((float)g_counts[i], 1.0f);
            }
            if (i == 0) g_offsets[n_nodes] = n_edges;
            __syncthreads();
        }
    }
    grid_bar(nb);

    // ======== P3: scatter + re-zero counts for next replay ========
    {
        int e4n = (n_edges + 3) >> 2;
        for (int c = gt; c < e4n; c += nthreads) {
            int i4 = c * 4;
            if (i4 + 4 <= n_edges) {
                int4 d = *(const int4*)(edst + i4);
                int4 sv = *(const int4*)(esrc + i4);
                int p0 = atomicAdd(&g_cursor[d.x], 1);
                int p1 = atomicAdd(&g_cursor[d.y], 1);
                int p2 = atomicAdd(&g_cursor[d.z], 1);
                int p3 = atomicAdd(&g_cursor[d.w], 1);
                g_nbr[p0] = sv.x; g_nbr[p1] = sv.y; g_nbr[p2] = sv.z; g_nbr[p3] = sv.w;
            } else {
                for (int i = i4; i < n_edges; ++i) {
                    int p = atomicAdd(&g_cursor[edst[i]], 1);
                    g_nbr[p] = esrc[i];
                }
            }
        }
        for (int i = gt; i <= n_nodes; i += nthreads) g_counts[i] = 0;
    }
    grid_bar(nb);

    // ======== P4: fused agg1 + gemmN + tanh + layer-2 projection ========
    #pragma unroll
    for (int r = 0; r < 4; ++r) {
        int idx = r * 256 + tid;
        *(float4*)&Wsh[idx * 4] = *(const float4*)(Wn1 + (size_t)idx * 4);
    }
    aux[tid] = Ws2[tid];          // ws2: aux[0..255]
    aux[256 + tid] = Wn2[tid];    // wn2: aux[256..511]
    if (tid < 4) aux[512 + tid] = b2[tid];
    __syncthreads();

    for (int tile = blockIdx.x; tile < n_tiles64; tile += nb) {
        int m0 = tile << 6;

        // Phase A: gather-mean into Ts. 4 threads/node: 2 col-halves x 2 edge-parities
        {
            int node = m0 + (tid >> 2);
            int sub  = tid & 3;
            int half = sub & 1;
            int eo   = sub >> 1;
            float acc[32];
            #pragma unroll
            for (int c = 0; c < 32; ++c) acc[c] = 0.f;

            if (node < n_nodes) {
                int beg = g_offsets[node];
                int end = g_offsets[node + 1];
                const __half* base = g_xh + half * 32;
                int e = beg + eo;
                for (; e + 2 < end; e += 4) {
                    int s0 = __ldg(&g_nbr[e]);
                    int s1 = __ldg(&g_nbr[e + 2]);
                    const uint4* r0 = (const uint4*)(base + (size_t)s0 * D);
                    const uint4* r1 = (const uint4*)(base + (size_t)s1 * D);
                    uint4 qa[4] = {r0[0], r0[1], r0[2], r0[3]};
                    uint4 qb[4] = {r1[0], r1[1], r1[2], r1[3]};
                    #pragma unroll
                    for (int qi = 0; qi < 4; ++qi) {
                        const __half2* ha = (const __half2*)&qa[qi];
                        const __half2* hb = (const __half2*)&qb[qi];
                        #pragma unroll
                        for (int j = 0; j < 4; ++j) {
                            float2 fa = __half22float2(ha[j]);
                            float2 fb = __half22float2(hb[j]);
                            acc[qi * 8 + 2 * j]     += fa.x + fb.x;
                            acc[qi * 8 + 2 * j + 1] += fa.y + fb.y;
                        }
                    }
                }
                if (e < end) {
                    int s0 = __ldg(&g_nbr[e]);
                    const uint4* r0 = (const uint4*)(base + (size_t)s0 * D);
                    #pragma unroll
                    for (int qi = 0; qi < 4; ++qi) {
                        uint4 q = r0[qi];
                        const __half2* ha = (const __half2*)&q;
                        #pragma unroll
                        for (int j = 0; j < 4; ++j) {
                            float2 fa = __half22float2(ha[j]);
                            acc[qi * 8 + 2 * j]     += fa.x;
                            acc[qi * 8 + 2 * j + 1] += fa.y;
                        }
                    }
                }
            }
            // combine the two edge-parities (lanes differ by 2)
            #pragma unroll
            for (int c = 0; c < 32; ++c)
                acc[c] += __shfl_xor_sync(0xffffffffu, acc[c], 2);
            if (sub < 2 && node < n_nodes) {
                float inv = g_invdeg[node];
                float* dst = &Ts[tid >> 2][half * 32];
                #pragma unroll
                for (int c = 0; c < 32; c += 4)
                    *(float4*)&dst[c] = make_float4(acc[c] * inv, acc[c + 1] * inv,
                                                    acc[c + 2] * inv, acc[c + 3] * inv);
            } else if (sub < 2 && (m0 + (tid >> 2)) < 64 + m0) {
                // zero-fill rows beyond n_nodes so GEMM reads defined data
                if (node >= n_nodes) {
                    float* dst = &Ts[tid >> 2][half * 32];
                    #pragma unroll
                    for (int c = 0; c < 32; c += 4)
                        *(float4*)&dst[c] = make_float4(0.f, 0.f, 0.f, 0.f);
                }
            }
        }
        __syncthreads();

        // Phase B: GEMM (Agg @ Wn1) + tanh(s1 + .) -> Ts
        unsigned long long acc2[8];
        #pragma unroll
        for (int i = 0; i < 8; ++i) acc2[i] = 0ULL;
        #pragma unroll
        for (int k0 = 0; k0 < 64; k0 += 4) {
            float4 wv[4];
            #pragma unroll
            for (int kk = 0; kk < 4; ++kk)
                wv[kk] = *(const float4*)&Wsh[(k0 + kk) * 64 + tx * 4];
            #pragma unroll
            for (int i = 0; i < 4; ++i) {
                float4 a4 = *(const float4*)&Ts[ty * 4 + i][k0];
                float av[4] = {a4.x, a4.y, a4.z, a4.w};
                #pragma unroll
                for (int kk = 0; kk < 4; ++kk) {
                    unsigned long long aa = pk2(av[kk], av[kk]);
                    fma2(acc2[i * 2],     aa, pk2(wv[kk].x, wv[kk].y));
                    fma2(acc2[i * 2 + 1], aa, pk2(wv[kk].z, wv[kk].w));
                }
            }
        }
        float h1v[4][4];
        #pragma unroll
        for (int i = 0; i < 4; ++i) {
            int m = m0 + ty * 4 + i;
            float2 r01 = upk2(acc2[i * 2]);
            float2 r23 = upk2(acc2[i * 2 + 1]);
            float4 s = make_float4(0.f, 0.f, 0.f, 0.f);
            if (m < n_nodes) s = *(const float4*)(g_s1 + (size_t)m * D + tx * 4);
            h1v[i][0] = tanhf(r01.x + s.x);
            h1v[i][1] = tanhf(r01.y + s.y);
            h1v[i][2] = tanhf(r23.x + s.z);
            h1v[i][3] = tanhf(r23.y + s.w);
        }
        __syncthreads();
        #pragma unroll
        for (int i = 0; i < 4; ++i)
            *(float4*)&Ts[ty * 4 + i][tx * 4] =
                make_float4(h1v[i][0], h1v[i][1], h1v[i][2], h1v[i][3]);
        __syncthreads();

        // Phase C: s = h1@Ws2+b2, z = h1@Wn2 (4 threads/node, 16 k each)
        {
            int row = tid >> 2;
            int sub = tid & 3;
            float s0 = 0.f, s1v = 0.f, s2 = 0.f, s3 = 0.f;
            float z0 = 0.f, z1 = 0.f, z2 = 0.f, z3 = 0.f;
            const float* hr = &Ts[row][sub * 16];
            #pragma unroll
            for (int k = 0; k < 16; ++k) {
                float h = hr[k];
                int kk = sub * 16 + k;
                float4 w = *(const float4*)&aux[kk * 4];
                float4 v = *(const float4*)&aux[256 + kk * 4];
                s0 += h * w.x; s1v += h * w.y; s2 += h * w.z; s3 += h * w.w;
                z0 += h * v.x; z1  += h * v.y; z2 += h * v.z; z3 += h * v.w;
            }
            #pragma unroll
            for (int o = 1; o <= 2; o <<= 1) {
                s0 += __shfl_xor_sync(0xffffffffu, s0, o);
                s1v += __shfl_xor_sync(0xffffffffu, s1v, o);
                s2 += __shfl_xor_sync(0xffffffffu, s2, o);
                s3 += __shfl_xor_sync(0xffffffffu, s3, o);
                z0 += __shfl_xor_sync(0xffffffffu, z0, o);
                z1 += __shfl_xor_sync(0xffffffffu, z1, o);
                z2 += __shfl_xor_sync(0xffffffffu, z2, o);
                z3 += __shfl_xor_sync(0xffffffffu, z3, o);
            }
            int m = m0 + row;
            if (sub == 0 && m < n_nodes) {
                g_s[m] = make_float4(s0 + aux[512], s1v + aux[513],
                                     s2 + aux[514], s3 + aux[515]);
                g_z[m] = make_float4(z0, z1, z2, z3);
            }
        }
        __syncthreads();
    }
    grid_bar(nb);

    // ======== P5: layer-2 aggregation (4 threads/node) + finalize ========
    {
        int n4 = n_nodes * 4;
        for (int t = gt; t < n4; t += nthreads) {
            int n = t >> 2;
            int sub = t & 3;
            int beg = g_offsets[n];
            int end = g_offsets[n + 1];
            float4 acc = make_float4(0.f, 0.f, 0.f, 0.f);
            for (int e = beg + sub; e < end; e += 4) {
                float4 a = g_z[__ldg(&g_nbr[e])];
                acc.x += a.x; acc.y += a.y; acc.z += a.z; acc.w += a.w;
            }
            #pragma unroll
            for (int o = 1; o <= 2; o <<= 1) {
                acc.x += __shfl_xor_sync(0xffffffffu, acc.x, o);
                acc.y += __shfl_xor_sync(0xffffffffu, acc.y, o);
                acc.z += __shfl_xor_sync(0xffffffffu, acc.z, o);
                acc.w += __shfl_xor_sync(0xffffffffu, acc.w, o);
            }
            if (sub == 0) {
                float inv = g_invdeg[n];
                float4 s = g_s[n];
                float4 o = make_float4(s.x + acc.x * inv, s.y + acc.y * inv,
                                       s.z + acc.z * inv, s.w + acc.w * inv);
                *(float4*)(out + (size_t)n * 4) = o;
            }
        }
    }
}

// ---------------- launch ----------------
extern "C" void kernel_launch(void* const* d_in, const int* in_sizes, int n_in,
                              void* d_out, int out_size) {
    const float* x    = (const float*)d_in[0];
    const int*   esrc = (const int*)d_in[1];
    const int*   edst = (const int*)d_in[2];
    const float* Ws1  = (const float*)d_in[3];
    const float* b1   = (const float*)d_in[4];
    const float* Wn1  = (const float*)d_in[5];
    const float* Ws2  = (const float*)d_in[6];
    const float* b2   = (const float*)d_in[7];
    const float* Wn2  = (const float*)d_in[8];
    float* out = (float*)d_out;

    int n_nodes = in_sizes[0] / D;
    int n_edges = in_sizes[1];

    mega_kernel<<<MEGA_BLOCKS, 256>>>(x, esrc, edst, Ws1, b1, Wn1,
                                      Ws2, b2, Wn2, out, n_nodes, n_edges);
}

// round 10
// speedup vs baseline: 1.8066x; 1.8066x over previous
#include <cuda_runtime.h>
#include <cuda_fp16.h>
#include <cuda_bf16.h>
#include <cstdint>

#define MAX_NODES 100000
#define MAX_EDGES 1600000
#define D 64

// ---------------- scratch (device globals) ----------------
__device__ int    g_counts[MAX_NODES + 1];   // zero on entry (BSS; re-zeroed in scatter)
__device__ int    g_offsets[MAX_NODES];
__device__ int    g_end[MAX_NODES];
__device__ float  g_invdeg[MAX_NODES];
__device__ int    g_nbr[MAX_EDGES];
__device__ int    g_rank[MAX_EDGES];
__device__ int    g_total;                   // zero on entry; re-zeroed in scatter
__device__ __half g_xh[(size_t)MAX_NODES * D];
__device__ float  g_s1[(size_t)MAX_NODES * D];
__device__ float4 g_z[MAX_NODES];
__device__ float4 g_s[MAX_NODES];

// ---------------- f32x2 packed helpers (sm_103a) ----------------
__device__ __forceinline__ unsigned long long pk2(float lo, float hi) {
    unsigned long long r;
    asm("mov.b64 %0, {%1, %2};" : "=l"(r) : "f"(lo), "f"(hi));
    return r;
}
__device__ __forceinline__ void fma2(unsigned long long& acc,
                                     unsigned long long a, unsigned long long b) {
    asm("fma.rn.f32x2 %0, %1, %2, %0;" : "+l"(acc) : "l"(a), "l"(b));
}
__device__ __forceinline__ float2 upk2(unsigned long long v) {
    float2 f;
    asm("mov.b64 {%0, %1}, %2;" : "=f"(f.x), "=f"(f.y) : "l"(v));
    return f;
}

// ---------------- CSR: histogram + per-edge rank (counts zero on entry) --------
__global__ void hist_kernel(const int* __restrict__ edge_dst, int n_edges) {
    int i4 = (blockIdx.x * blockDim.x + threadIdx.x) * 4;
    if (i4 + 4 <= n_edges) {
        int4 d = *(const int4*)(edge_dst + i4);
        int4 r;
        r.x = atomicAdd(&g_counts[d.x], 1);
        r.y = atomicAdd(&g_counts[d.y], 1);
        r.z = atomicAdd(&g_counts[d.z], 1);
        r.w = atomicAdd(&g_counts[d.w], 1);
        *(int4*)(g_rank + i4) = r;
    } else {
        for (int i = i4; i < n_edges; ++i)
            g_rank[i] = atomicAdd(&g_counts[edge_dst[i]], 1);
    }
}

// ---------------- CSR: single-pass scan (local scan + atomic block base) --------
__global__ __launch_bounds__(256) void scanAB_kernel(int n_nodes) {
    __shared__ int wsum[8];
    __shared__ int base_sh;
    int i = blockIdx.x * 256 + threadIdx.x;
    int c = (i < n_nodes) ? g_counts[i] : 0;
    int lane = threadIdx.x & 31, wid = threadIdx.x >> 5;
    int v = c;
    #pragma unroll
    for (int o = 1; o < 32; o <<= 1) {
        int u = __shfl_up_sync(0xffffffffu, v, o);
        if (lane >= o) v += u;
    }
    if (lane == 31) wsum[wid] = v;
    __syncthreads();
    if (wid == 0) {
        int w = (lane < 8) ? wsum[lane] : 0;
        #pragma unroll
        for (int o = 1; o < 8; o <<= 1) {
            int u = __shfl_up_sync(0xffffffffu, w, o);
            if (lane >= o) w += u;
        }
        if (lane < 8) wsum[lane] = w;
    }
    __syncthreads();
    int wbase = (wid > 0) ? wsum[wid - 1] : 0;
    int incl = v + wbase;                       // tile-local inclusive
    if (threadIdx.x == 255) base_sh = atomicAdd(&g_total, incl);  // tile total
    __syncthreads();
    int base = base_sh;
    if (i < n_nodes) {
        int off = base + incl - c;
        g_offsets[i] = off;
        g_end[i]     = base + incl;
        g_invdeg[i]  = 1.0f / fmaxf((float)c, 1.0f);
    }
}

// ---------------- CSR: atomic-free scatter + re-zero for next replay ----------
__global__ void scatter_kernel(const int* __restrict__ edge_src,
                               const int* __restrict__ edge_dst,
                               int n_nodes, int n_edges) {
    int gt = blockIdx.x * blockDim.x + threadIdx.x;
    int i4 = gt * 4;
    if (i4 + 4 <= n_edges) {
        int4 d  = *(const int4*)(edge_dst + i4);
        int4 sv = *(const int4*)(edge_src + i4);
        int4 r  = *(const int4*)(g_rank + i4);
        g_nbr[g_offsets[d.x] + r.x] = sv.x;
        g_nbr[g_offsets[d.y] + r.y] = sv.y;
        g_nbr[g_offsets[d.z] + r.z] = sv.z;
        g_nbr[g_offsets[d.w] + r.w] = sv.w;
    } else {
        for (int i = i4; i < n_edges; ++i)
            g_nbr[g_offsets[edge_dst[i]] + g_rank[i]] = edge_src[i];
    }
    // counts/total are dead after scanAB — re-zero for the next graph replay
    int nthreads = gridDim.x * blockDim.x;
    for (int i = gt; i <= n_nodes; i += nthreads) g_counts[i] = 0;
    if (gt == 0) g_total = 0;
}

// ---------------- gemm0: g_s1 = X@Ws1 + b1, also emits fp16 copy of X ----------
__global__ __launch_bounds__(256) void gemm0_kernel(const float* __restrict__ X,
                                                    const float* __restrict__ W,
                                                    const float* __restrict__ bias,
                                                    int n_nodes) {
    __shared__ float Ts[128][68];
    __shared__ float Wsh[64 * 64];
    __shared__ float bsh[64];

    int tid = threadIdx.x;
    int tx  = tid & 15;
    int ty  = tid >> 4;
    int m0  = blockIdx.x * 128;

    if (tid < 64) bsh[tid] = bias[tid];

    int mrow = tid >> 4;
    int col4 = tid & 15;
    #pragma unroll
    for (int r = 0; r < 8; ++r) {
        int m = r * 16 + mrow;
        int gm = m0 + m;
        float4 v = make_float4(0.f, 0.f, 0.f, 0.f);
        if (gm < n_nodes) {
            v = *(const float4*)(X + (size_t)gm * D + col4 * 4);
            __half2 h0 = __floats2half2_rn(v.x, v.y);
            __half2 h1 = __floats2half2_rn(v.z, v.w);
            uint2 o;
            o.x = *(unsigned int*)&h0;
            o.y = *(unsigned int*)&h1;
            *(uint2*)(g_xh + (size_t)gm * D + col4 * 4) = o;
        }
        *(float4*)&Ts[m][col4 * 4] = v;
    }
    #pragma unroll
    for (int r = 0; r < 4; ++r) {
        int idx = r * 256 + tid;
        *(float4*)&Wsh[idx * 4] = *(const float4*)(W + (size_t)idx * 4);
    }
    __syncthreads();

    unsigned long long acc2[16];
    #pragma unroll
    for (int i = 0; i < 16; ++i) acc2[i] = 0ULL;

    #pragma unroll
    for (int k0 = 0; k0 < 64; k0 += 4) {
        float4 wv[4];
        #pragma unroll
        for (int kk = 0; kk < 4; ++kk)
            wv[kk] = *(const float4*)&Wsh[(k0 + kk) * 64 + tx * 4];
        #pragma unroll
        for (int i = 0; i < 8; ++i) {
            float4 a4 = *(const float4*)&Ts[ty * 8 + i][k0];
            float av[4] = {a4.x, a4.y, a4.z, a4.w};
            #pragma unroll
            for (int kk = 0; kk < 4; ++kk) {
                unsigned long long aa = pk2(av[kk], av[kk]);
                fma2(acc2[i * 2],     aa, pk2(wv[kk].x, wv[kk].y));
                fma2(acc2[i * 2 + 1], aa, pk2(wv[kk].z, wv[kk].w));
            }
        }
    }

    #pragma unroll
    for (int i = 0; i < 8; ++i) {
        int m = m0 + ty * 8 + i;
        if (m >= n_nodes) continue;
        float2 r01 = upk2(acc2[i * 2]);
        float2 r23 = upk2(acc2[i * 2 + 1]);
        float4 o;
        o.x = r01.x + bsh[tx * 4 + 0];
        o.y = r01.y + bsh[tx * 4 + 1];
        o.z = r23.x + bsh[tx * 4 + 2];
        o.w = r23.y + bsh[tx * 4 + 3];
        *(float4*)(g_s1 + (size_t)m * D + tx * 4) = o;
    }
}

// ---------------- fused: agg1 + gemmN + tanh + layer-2 projection ----------------
__global__ __launch_bounds__(256) void fused_kernel(const float* __restrict__ Wn1,
                                                    const float* __restrict__ Ws2,
                                                    const float* __restrict__ b2,
                                                    const float* __restrict__ Wn2,
                                                    int n_nodes) {
    __shared__ float Ts[128][68];
    __shared__ float Wsh[64 * 64];
    __shared__ float ws2[256], wn2[256], bs2[4];

    int tid = threadIdx.x;
    int m0  = blockIdx.x * 128;

    #pragma unroll
    for (int r = 0; r < 4; ++r) {
        int idx = r * 256 + tid;
        *(float4*)&Wsh[idx * 4] = *(const float4*)(Wn1 + (size_t)idx * 4);
    }
    ws2[tid] = Ws2[tid];
    wn2[tid] = Wn2[tid];
    if (tid < 4) bs2[tid] = b2[tid];

    // ---- Phase A: gather-mean into Ts ----
    {
        int node = m0 + (tid >> 1);
        int half = tid & 1;
        float acc[32];
        #pragma unroll
        for (int c = 0; c < 32; ++c) acc[c] = 0.f;

        if (node < n_nodes) {
            int beg = g_offsets[node];
            int end = g_end[node];
            const __half* base = g_xh + half * 32;
            int e = beg;
            for (; e + 2 <= end; e += 2) {
                int s0 = __ldg(&g_nbr[e]);
                int s1 = __ldg(&g_nbr[e + 1]);
                const uint4* r0 = (const uint4*)(base + (size_t)s0 * D);
                const uint4* r1 = (const uint4*)(base + (size_t)s1 * D);
                uint4 qa[4] = {r0[0], r0[1], r0[2], r0[3]};
                uint4 qb[4] = {r1[0], r1[1], r1[2], r1[3]};
                #pragma unroll
                for (int qi = 0; qi < 4; ++qi) {
                    const __half2* ha = (const __half2*)&qa[qi];
                    const __half2* hb = (const __half2*)&qb[qi];
                    #pragma unroll
                    for (int j = 0; j < 4; ++j) {
                        float2 fa = __half22float2(ha[j]);
                        float2 fb = __half22float2(hb[j]);
                        acc[qi * 8 + 2 * j]     += fa.x + fb.x;
                        acc[qi * 8 + 2 * j + 1] += fa.y + fb.y;
                    }
                }
            }
            if (e < end) {
                int s0 = __ldg(&g_nbr[e]);
                const uint4* r0 = (const uint4*)(base + (size_t)s0 * D);
                #pragma unroll
                for (int qi = 0; qi < 4; ++qi) {
                    uint4 q = r0[qi];
                    const __half2* ha = (const __half2*)&q;
                    #pragma unroll
                    for (int j = 0; j < 4; ++j) {
                        float2 fa = __half22float2(ha[j]);
                        acc[qi * 8 + 2 * j]     += fa.x;
                        acc[qi * 8 + 2 * j + 1] += fa.y;
                    }
                }
            }
            float inv = g_invdeg[node];
            #pragma unroll
            for (int c = 0; c < 32; ++c) acc[c] *= inv;
        }
        float* dst = &Ts[tid >> 1][half * 32];
        #pragma unroll
        for (int c = 0; c < 32; c += 4)
            *(float4*)&dst[c] = make_float4(acc[c], acc[c + 1], acc[c + 2], acc[c + 3]);
    }
    __syncthreads();

    // ---- Phase B: GEMM + tanh(s1 + .) -> Ts ----
    int tx = tid & 15;
    int ty = tid >> 4;
    unsigned long long acc2[16];
    #pragma unroll
    for (int i = 0; i < 16; ++i) acc2[i] = 0ULL;

    #pragma unroll
    for (int k0 = 0; k0 < 64; k0 += 4) {
        float4 wv[4];
        #pragma unroll
        for (int kk = 0; kk < 4; ++kk)
            wv[kk] = *(const float4*)&Wsh[(k0 + kk) * 64 + tx * 4];
        #pragma unroll
        for (int i = 0; i < 8; ++i) {
            float4 a4 = *(const float4*)&Ts[ty * 8 + i][k0];
            float av[4] = {a4.x, a4.y, a4.z, a4.w};
            #pragma unroll
            for (int kk = 0; kk < 4; ++kk) {
                unsigned long long aa = pk2(av[kk], av[kk]);
                fma2(acc2[i * 2],     aa, pk2(wv[kk].x, wv[kk].y));
                fma2(acc2[i * 2 + 1], aa, pk2(wv[kk].z, wv[kk].w));
            }
        }
    }

    float h1v[8][4];
    #pragma unroll
    for (int i = 0; i < 8; ++i) {
        int m = m0 + ty * 8 + i;
        float2 r01 = upk2(acc2[i * 2]);
        float2 r23 = upk2(acc2[i * 2 + 1]);
        float4 s = make_float4(0.f, 0.f, 0.f, 0.f);
        if (m < n_nodes) s = *(const float4*)(g_s1 + (size_t)m * D + tx * 4);
        h1v[i][0] = tanhf(r01.x + s.x);
        h1v[i][1] = tanhf(r01.y + s.y);
        h1v[i][2] = tanhf(r23.x + s.z);
        h1v[i][3] = tanhf(r23.y + s.w);
    }
    __syncthreads();
    #pragma unroll
    for (int i = 0; i < 8; ++i)
        *(float4*)&Ts[ty * 8 + i][tx * 4] =
            make_float4(h1v[i][0], h1v[i][1], h1v[i][2], h1v[i][3]);
    __syncthreads();

    // ---- Phase C: project to s (self+bias) and z (neigh) ----
    {
        int row  = tid >> 1;
        int half = tid & 1;
        float s0 = 0.f, s1v = 0.f, s2 = 0.f, s3 = 0.f;
        float z0 = 0.f, z1 = 0.f, z2 = 0.f, z3 = 0.f;
        const float* hr = &Ts[row][half * 32];
        #pragma unroll
        for (int k = 0; k < 32; ++k) {
            float h = hr[k];
            int kk = half * 32 + k;
            float4 w = *(const float4*)&ws2[kk * 4];
            float4 v = *(const float4*)&wn2[kk * 4];
            s0 += h * w.x; s1v += h * w.y; s2 += h * w.z; s3 += h * w.w;
            z0 += h * v.x; z1  += h * v.y; z2 += h * v.z; z3 += h * v.w;
        }
        s0 += __shfl_xor_sync(0xffffffffu, s0, 1);
        s1v += __shfl_xor_sync(0xffffffffu, s1v, 1);
        s2 += __shfl_xor_sync(0xffffffffu, s2, 1);
        s3 += __shfl_xor_sync(0xffffffffu, s3, 1);
        z0 += __shfl_xor_sync(0xffffffffu, z0, 1);
        z1 += __shfl_xor_sync(0xffffffffu, z1, 1);
        z2 += __shfl_xor_sync(0xffffffffu, z2, 1);
        z3 += __shfl_xor_sync(0xffffffffu, z3, 1);
        int m = m0 + row;
        if (half == 0 && m < n_nodes) {
            g_s[m] = make_float4(s0 + bs2[0], s1v + bs2[1], s2 + bs2[2], s3 + bs2[3]);
            g_z[m] = make_float4(z0, z1, z2, z3);
        }
    }
}

// ---------------- layer-2 aggregation: 4 threads per node ----------------
__global__ __launch_bounds__(256) void agg2_kernel(float* __restrict__ out,
                                                   int n_nodes) {
    int t   = blockIdx.x * blockDim.x + threadIdx.x;
    int n   = t >> 2;
    int sub = t & 3;
    if (n >= n_nodes) return;
    int beg = g_offsets[n];
    int end = g_end[n];
    float4 acc = make_float4(0.f, 0.f, 0.f, 0.f);
    for (int e = beg + sub; e < end; e += 4) {
        float4 a = g_z[__ldg(&g_nbr[e])];
        acc.x += a.x; acc.y += a.y; acc.z += a.z; acc.w += a.w;
    }
    #pragma unroll
    for (int o = 1; o <= 2; o <<= 1) {
        acc.x += __shfl_xor_sync(0xffffffffu, acc.x, o);
        acc.y += __shfl_xor_sync(0xffffffffu, acc.y, o);
        acc.z += __shfl_xor_sync(0xffffffffu, acc.z, o);
        acc.w += __shfl_xor_sync(0xffffffffu, acc.w, o);
    }
    if (sub == 0) {
        float inv = g_invdeg[n];
        float4 s = g_s[n];
        float4 o = make_float4(s.x + acc.x * inv, s.y + acc.y * inv,
                               s.z + acc.z * inv, s.w + acc.w * inv);
        *(float4*)(out + (size_t)n * 4) = o;
    }
}

// ---------------- side stream ----------------
namespace {
struct Ctx {
    cudaStream_t s2;
    cudaEvent_t eFork, eJoin;
    Ctx() {
        cudaStreamCreate(&s2);
        cudaEventCreateWithFlags(&eFork, cudaEventDisableTiming);
        cudaEventCreateWithFlags(&eJoin, cudaEventDisableTiming);
    }
};
Ctx g_ctx;
}

// ---------------- launch ----------------
extern "C" void kernel_launch(void* const* d_in, const int* in_sizes, int n_in,
                              void* d_out, int out_size) {
    const float* x    = (const float*)d_in[0];
    const int*   esrc = (const int*)d_in[1];
    const int*   edst = (const int*)d_in[2];
    const float* Ws1  = (const float*)d_in[3];
    const float* b1   = (const float*)d_in[4];
    const float* Wn1  = (const float*)d_in[5];
    const float* Ws2  = (const float*)d_in[6];
    const float* b2   = (const float*)d_in[7];
    const float* Wn2  = (const float*)d_in[8];
    float* out = (float*)d_out;

    int n_nodes = in_sizes[0] / D;
    int n_edges = in_sizes[1];
    int np = (n_nodes + 255) / 256;
    int e4_blocks = ((n_edges + 3) / 4 + 255) / 256;
    int gemm_blocks = (n_nodes + 127) / 128;

    // fork: side stream runs self-GEMM (+fp16 emit) under the CSR build
    cudaEventRecord(g_ctx.eFork, 0);
    cudaStreamWaitEvent(g_ctx.s2, g_ctx.eFork, 0);
    gemm0_kernel<<<gemm_blocks, 256, 0, g_ctx.s2>>>(x, Ws1, b1, n_nodes);
    cudaEventRecord(g_ctx.eJoin, g_ctx.s2);

    // main: CSR build (counts/total zero: BSS first run, re-zeroed by scatter)
    hist_kernel<<<e4_blocks, 256>>>(edst, n_edges);
    scanAB_kernel<<<np, 256>>>(n_nodes);
    scatter_kernel<<<e4_blocks, 256>>>(esrc, edst, n_nodes, n_edges);

    // join: fused needs g_xh + g_s1 from stream2
    cudaStreamWaitEvent(0, g_ctx.eJoin, 0);

    fused_kernel<<<gemm_blocks, 256>>>(Wn1, Ws2, b2, Wn2, n_nodes);
    agg2_kernel<<<(n_nodes * 4 + 255) / 256, 256>>>(out, n_nodes);
}